// round 4
// baseline (speedup 1.0000x reference)
#include <cuda_runtime.h>

// Problem constants: B=8, L=1024, D=512, T=16
#define M_ROWS 8192          // B*L
#define K_DIM  512           // D
#define N_COLS 8192          // D*T
#define T_STEPS 16
#define PER_T_COUNT 4194304  // M_ROWS * D  (elements per BN channel)

typedef unsigned long long u64;

// ---------------- scratch (static device globals; no allocation) ----------
__device__ float g_xn[M_ROWS * K_DIM];               // 16 MB  layernormed input
__device__ float g_y[(size_t)M_ROWS * N_COLS];       // 256 MB GEMM output
__device__ float g_part[M_ROWS * 32];                // per-row BN partials
__device__ float g_bin[32];                          // reduced sums / sumsq
__device__ float g_stats[32];                        // mean[16], invstd[16]

// ---------------- packed f32x2 helpers (FFMA2 path, sm_103a) --------------
__device__ __forceinline__ u64 pack_dup(float a) {
    u64 r; asm("mov.b64 %0, {%1, %1};" : "=l"(r) : "f"(a)); return r;
}
__device__ __forceinline__ void fma2(u64& c, u64 a, u64 b) {
    asm("fma.rn.f32x2 %0, %1, %2, %0;" : "+l"(c) : "l"(a), "l"(b));
}
__device__ __forceinline__ float2 unpack2(u64 v) {
    float2 f; asm("mov.b64 {%0, %1}, %2;" : "=f"(f.x), "=f"(f.y) : "l"(v)); return f;
}

// ---------------- 1. LayerNorm over D ------------------------------------
__global__ __launch_bounds__(128) void ln_kernel(const float* __restrict__ x,
                                                 const float* __restrict__ g,
                                                 const float* __restrict__ bb) {
    const int row = blockIdx.x;
    const int tid = threadIdx.x;
    const unsigned lane = tid & 31, wid = tid >> 5;
    __shared__ float r4[4];

    const float4* xr = (const float4*)(x + (size_t)row * K_DIM);
    float4 v = xr[tid];

    float s = (v.x + v.y) + (v.z + v.w);
    #pragma unroll
    for (int o = 16; o; o >>= 1) s += __shfl_xor_sync(0xffffffffu, s, o);
    if (!lane) r4[wid] = s;
    __syncthreads();
    float mean = (r4[0] + r4[1] + r4[2] + r4[3]) * (1.0f / 512.0f);
    __syncthreads();

    float dx = v.x - mean, dy = v.y - mean, dz = v.z - mean, dw = v.w - mean;
    float q = (dx * dx + dy * dy) + (dz * dz + dw * dw);
    #pragma unroll
    for (int o = 16; o; o >>= 1) q += __shfl_xor_sync(0xffffffffu, q, o);
    if (!lane) r4[wid] = q;
    __syncthreads();
    float var = (r4[0] + r4[1] + r4[2] + r4[3]) * (1.0f / 512.0f);
    float rstd = 1.0f / sqrtf(var + 1e-5f);

    const int c = tid * 4;
    float4 o4;
    o4.x = dx * rstd * g[c + 0] + bb[c + 0];
    o4.y = dy * rstd * g[c + 1] + bb[c + 1];
    o4.z = dz * rstd * g[c + 2] + bb[c + 2];
    o4.w = dw * rstd * g[c + 3] + bb[c + 3];
    ((float4*)(g_xn + (size_t)row * K_DIM))[tid] = o4;
}

// ---------------- 2. fp32 GEMM: C = xn @ W^T + bias -----------------------
// 128x128x16 tiles, 8x8 per thread, FFMA2 packed accumulators (pairs along N)
__global__ __launch_bounds__(256, 2) void gemm_kernel(const float* __restrict__ Wm,
                                                      const float* __restrict__ bias) {
    __shared__ float As[16][128];
    __shared__ float Bs[16][128];

    const int tid  = threadIdx.x;
    const int brow = blockIdx.y << 7;
    const int bcol = blockIdx.x << 7;
    const int tx = tid & 15;          // N sub-tile
    const int ty = tid >> 4;          // M sub-tile
    const int lrow = tid >> 2;        // 0..63 (loader row; also +64)
    const int lk   = (tid & 3) << 2;  // 0,4,8,12 (loader k base)

    u64 acc[8][4];
    #pragma unroll
    for (int i = 0; i < 8; i++)
        #pragma unroll
        for (int j = 0; j < 4; j++) acc[i][j] = 0ull;

    const float* Ag = g_xn + (size_t)(brow + lrow) * K_DIM + lk;
    const float* Bg = Wm   + (size_t)(bcol + lrow) * K_DIM + lk;

    for (int kk = 0; kk < K_DIM; kk += 16) {
        float4 a0 = *(const float4*)(Ag + kk);
        float4 a1 = *(const float4*)(Ag + kk + (size_t)64 * K_DIM);
        float4 b0 = *(const float4*)(Bg + kk);
        float4 b1 = *(const float4*)(Bg + kk + (size_t)64 * K_DIM);
        __syncthreads();
        As[lk + 0][lrow] = a0.x; As[lk + 1][lrow] = a0.y;
        As[lk + 2][lrow] = a0.z; As[lk + 3][lrow] = a0.w;
        As[lk + 0][lrow + 64] = a1.x; As[lk + 1][lrow + 64] = a1.y;
        As[lk + 2][lrow + 64] = a1.z; As[lk + 3][lrow + 64] = a1.w;
        Bs[lk + 0][lrow] = b0.x; Bs[lk + 1][lrow] = b0.y;
        Bs[lk + 2][lrow] = b0.z; Bs[lk + 3][lrow] = b0.w;
        Bs[lk + 0][lrow + 64] = b1.x; Bs[lk + 1][lrow + 64] = b1.y;
        Bs[lk + 2][lrow + 64] = b1.z; Bs[lk + 3][lrow + 64] = b1.w;
        __syncthreads();

        #pragma unroll
        for (int k = 0; k < 16; ++k) {
            float4 af0 = *(const float4*)&As[k][ty << 3];
            float4 af1 = *(const float4*)&As[k][(ty << 3) + 4];
            ulonglong2 bb0 = *(const ulonglong2*)&Bs[k][tx << 3];
            ulonglong2 bb1 = *(const ulonglong2*)&Bs[k][(tx << 3) + 4];
            u64 b2[4] = {bb0.x, bb0.y, bb1.x, bb1.y};
            float av[8] = {af0.x, af0.y, af0.z, af0.w, af1.x, af1.y, af1.z, af1.w};
            #pragma unroll
            for (int i = 0; i < 8; i++) {
                u64 a2 = pack_dup(av[i]);
                fma2(acc[i][0], a2, b2[0]);
                fma2(acc[i][1], a2, b2[1]);
                fma2(acc[i][2], a2, b2[2]);
                fma2(acc[i][3], a2, b2[3]);
            }
        }
    }

    float bv[8];
    #pragma unroll
    for (int j = 0; j < 8; j++) bv[j] = bias[bcol + (tx << 3) + j];

    #pragma unroll
    for (int i = 0; i < 8; i++) {
        float* cp = g_y + (size_t)(brow + (ty << 3) + i) * N_COLS + bcol + (tx << 3);
        float2 f0 = unpack2(acc[i][0]);
        float2 f1 = unpack2(acc[i][1]);
        float2 f2 = unpack2(acc[i][2]);
        float2 f3 = unpack2(acc[i][3]);
        float4 o0 = {f0.x + bv[0], f0.y + bv[1], f1.x + bv[2], f1.y + bv[3]};
        float4 o1 = {f2.x + bv[4], f2.y + bv[5], f3.x + bv[6], f3.y + bv[7]};
        *(float4*)cp = o0;
        *(float4*)(cp + 4) = o1;
    }
}

// ---------------- 3. BN stats: per-row partial sums per t = col & 15 ------
__global__ __launch_bounds__(256) void stats_kernel() {
    const int row = blockIdx.x;
    const int tid = threadIdx.x;
    const float* yr = g_y + (size_t)row * N_COLS;
    float s = 0.f, q = 0.f;
    #pragma unroll 8
    for (int j = 0; j < 32; j++) {
        float v = yr[tid + (j << 8)];   // col % 16 == tid % 16 for all j
        s += v;
        q += v * v;
    }
    __shared__ float sh[512];
    sh[tid] = s;
    sh[256 + tid] = q;
    __syncthreads();
    if (tid < 32) {
        const int base = (tid < 16) ? tid : (256 + tid - 16);
        float a = 0.f;
        #pragma unroll
        for (int j = 0; j < 16; j++) a += sh[base + (j << 4)];
        g_part[row * 32 + tid] = a;
    }
}

__global__ __launch_bounds__(256) void reduce_kernel() {
    const int bin = blockIdx.x;
    const int tid = threadIdx.x;
    float s = 0.f;
    for (int r = tid; r < M_ROWS; r += 256) s += g_part[r * 32 + bin];
    __shared__ float sh[256];
    sh[tid] = s;
    __syncthreads();
    #pragma unroll
    for (int o = 128; o; o >>= 1) {
        if (tid < o) sh[tid] += sh[tid + o];
        __syncthreads();
    }
    if (!tid) g_bin[bin] = sh[0];
}

__global__ void finalize_kernel() {
    const int t = threadIdx.x;  // 16 threads
    float mean = g_bin[t] * (1.0f / (float)PER_T_COUNT);
    float ex2  = g_bin[16 + t] * (1.0f / (float)PER_T_COUNT);
    float var  = ex2 - mean * mean;
    g_stats[t] = mean;
    g_stats[16 + t] = 1.0f / sqrtf(var + 1e-5f);
}

// ---------------- 4. BN normalize + LIF scan + spike write ----------------
__global__ __launch_bounds__(256) void lif_kernel(const float* __restrict__ bng,
                                                  const float* __restrict__ bnb,
                                                  const float* __restrict__ th,
                                                  float* __restrict__ out) {
    __shared__ float sm[16], si[16], sg[16], sb[16];
    const int tid = threadIdx.x;
    if (tid < 16) {
        sm[tid] = g_stats[tid];
        si[tid] = g_stats[16 + tid];
        sg[tid] = bng[tid];
        sb[tid] = bnb[tid];
    }
    __syncthreads();
    const float thr = __ldg(th);

    const unsigned gid = blockIdx.x * 256u + tid;  // 0 .. 4194303
    const unsigned m = gid >> 9;
    const unsigned d = gid & 511u;

    const float4* yp = (const float4*)(g_y + ((size_t)m << 13) + ((size_t)d << 4));
    float4 v0 = yp[0], v1 = yp[1], v2 = yp[2], v3 = yp[3];
    float xs[16] = {v0.x, v0.y, v0.z, v0.w, v1.x, v1.y, v1.z, v1.w,
                    v2.x, v2.y, v2.z, v2.w, v3.x, v3.y, v3.z, v3.w};

    float v = 0.f;
    const size_t ob = ((size_t)m << 9) + d;
    #pragma unroll
    for (int t = 0; t < T_STEPS; t++) {
        float val = (xs[t] - sm[t]) * si[t];
        val = val * sg[t] + sb[t];
        v = v + (val - v) * 0.5f;          // v += (x - v)/tau, tau=2 (exact /2)
        bool fire = (v >= thr);            // spike_fn(v - thr): (v-thr)>=0 <=> v>=thr
        out[ob + ((size_t)t << 22)] = fire ? 1.0f : 0.0f;
        if (fire) v = 0.f;                 // hard reset to 0
    }
}

// ---------------- launch ---------------------------------------------------
extern "C" void kernel_launch(void* const* d_in, const int* in_sizes, int n_in,
                              void* d_out, int out_size) {
    const float* x    = (const float*)d_in[0];  // inputs (B,L,D)
    const float* Wm   = (const float*)d_in[1];  // W (D*T, D)
    const float* bias = (const float*)d_in[2];  // b (D*T)
    const float* lng  = (const float*)d_in[3];
    const float* lnb  = (const float*)d_in[4];
    const float* bng  = (const float*)d_in[5];
    const float* bnb  = (const float*)d_in[6];
    const float* th   = (const float*)d_in[7];
    float* out = (float*)d_out;

    ln_kernel<<<M_ROWS, 128>>>(x, lng, lnb);
    dim3 gg(N_COLS / 128, M_ROWS / 128);
    gemm_kernel<<<gg, 256>>>(Wm, bias);
    stats_kernel<<<M_ROWS, 256>>>();
    reduce_kernel<<<32, 256>>>();
    finalize_kernel<<<1, 16>>>();
    lif_kernel<<<(M_ROWS * K_DIM) / 256, 256>>>(bng, bnb, th, out);
}

// round 7
// speedup vs baseline: 1.0738x; 1.0738x over previous
#include <cuda_runtime.h>

// Problem constants: B=8, L=1024, D=512, T=16
#define M_ROWS 8192          // B*L
#define K_DIM  512           // D
#define N_COLS 8192          // D*T
#define T_STEPS 16
#define PER_T_COUNT 4194304  // M_ROWS * D  (elements per BN channel)

typedef unsigned long long u64;

// ---------------- scratch (static device globals; no allocation) ----------
__device__ float g_xn[M_ROWS * K_DIM];               // 16 MB  layernormed input
__device__ float g_y[(size_t)M_ROWS * N_COLS];       // 256 MB GEMM output
__device__ float g_part[M_ROWS * 32];                // per-row BN partials
__device__ float g_bin[32];                          // reduced sums / sumsq
__device__ float g_stats[32];                        // mean[16], invstd[16]

// ---------------- packed f32x2 helpers (FFMA2 path, sm_103a) --------------
__device__ __forceinline__ void fma2(u64& c, u64 a, u64 b) {
    asm("fma.rn.f32x2 %0, %1, %2, %0;" : "+l"(c) : "l"(a), "l"(b));
}
__device__ __forceinline__ float2 unpack2(u64 v) {
    float2 f; asm("mov.b64 {%0, %1}, %2;" : "=f"(f.x), "=f"(f.y) : "l"(v)); return f;
}

// ---------------- 1. LayerNorm over D ------------------------------------
__global__ __launch_bounds__(128) void ln_kernel(const float* __restrict__ x,
                                                 const float* __restrict__ g,
                                                 const float* __restrict__ bb) {
    const int row = blockIdx.x;
    const int tid = threadIdx.x;
    const unsigned lane = tid & 31, wid = tid >> 5;
    __shared__ float r4[4];

    const float4* xr = (const float4*)(x + (size_t)row * K_DIM);
    float4 v = xr[tid];

    float s = (v.x + v.y) + (v.z + v.w);
    #pragma unroll
    for (int o = 16; o; o >>= 1) s += __shfl_xor_sync(0xffffffffu, s, o);
    if (!lane) r4[wid] = s;
    __syncthreads();
    float mean = (r4[0] + r4[1] + r4[2] + r4[3]) * (1.0f / 512.0f);
    __syncthreads();

    float dx = v.x - mean, dy = v.y - mean, dz = v.z - mean, dw = v.w - mean;
    float q = (dx * dx + dy * dy) + (dz * dz + dw * dw);
    #pragma unroll
    for (int o = 16; o; o >>= 1) q += __shfl_xor_sync(0xffffffffu, q, o);
    if (!lane) r4[wid] = q;
    __syncthreads();
    float var = (r4[0] + r4[1] + r4[2] + r4[3]) * (1.0f / 512.0f);
    float rstd = 1.0f / sqrtf(var + 1e-5f);

    const int c = tid * 4;
    float4 o4;
    o4.x = dx * rstd * g[c + 0] + bb[c + 0];
    o4.y = dy * rstd * g[c + 1] + bb[c + 1];
    o4.z = dz * rstd * g[c + 2] + bb[c + 2];
    o4.w = dw * rstd * g[c + 3] + bb[c + 3];
    ((float4*)(g_xn + (size_t)row * K_DIM))[tid] = o4;
}

// ---------------- 2. fp32 GEMM: C = xn @ W^T + bias -----------------------
// 128x128x16 tiles, 8x8 per thread, FFMA2 packed accumulators.
// A is stored DUPLICATED in SMEM ([a,a] pairs) so the FFMA2 broadcast
// operand comes straight from LDS.128 (no pack MOVs). Thread's N-columns are
// split {4tx, 64+4tx} so B LDS.128 addresses are contiguous (conflict-free).
// Double-buffered SMEM: one __syncthreads per K-tile.
// NOTE: per-output accumulation order is IDENTICAL to the R3 kernel ->
// g_y is bitwise identical -> spikes bitwise identical.
#define A_STRIDE 260   // floats per k-row of dup'd A (256 data + pad, 16B-aligned)
#define B_STRIDE 132   // floats per k-row of B (128 data + pad, 16B-aligned)

__global__ __launch_bounds__(256, 2) void gemm_kernel(const float* __restrict__ Wm,
                                                      const float* __restrict__ bias) {
    __shared__ float As2[2][16 * A_STRIDE];   // ~33.3 KB
    __shared__ float Bs [2][16 * B_STRIDE];   // ~16.9 KB

    const int tid  = threadIdx.x;
    const int brow = blockIdx.y << 7;
    const int bcol = blockIdx.x << 7;
    const int tx = tid & 15;          // N sub-tile: cols {4tx..4tx+3, 64+4tx..+3}
    const int ty = tid >> 4;          // M sub-tile: rows {4ty..4ty+3, 64+4ty..+3}
    const int lrow = tid >> 2;        // 0..63 (loader row; also +64)
    const int lk   = (tid & 3) << 2;  // 0,4,8,12 (loader k base)

    u64 acc[8][4];
    #pragma unroll
    for (int i = 0; i < 8; i++)
        #pragma unroll
        for (int j = 0; j < 4; j++) acc[i][j] = 0ull;

    const float* Ag = g_xn + (size_t)(brow + lrow) * K_DIM + lk;
    const float* Bg = Wm   + (size_t)(bcol + lrow) * K_DIM + lk;

    // ---- prologue: load + store tile 0 ----
    {
        float4 a0 = *(const float4*)(Ag);
        float4 a1 = *(const float4*)(Ag + (size_t)64 * K_DIM);
        float4 b0 = *(const float4*)(Bg);
        float4 b1 = *(const float4*)(Bg + (size_t)64 * K_DIM);
        float av0[4] = {a0.x, a0.y, a0.z, a0.w};
        float av1[4] = {a1.x, a1.y, a1.z, a1.w};
        float bv0[4] = {b0.x, b0.y, b0.z, b0.w};
        float bv1[4] = {b1.x, b1.y, b1.z, b1.w};
        #pragma unroll
        for (int j = 0; j < 4; j++) {
            const int kr = lk + j;
            float2 d0 = {av0[j], av0[j]};
            float2 d1 = {av1[j], av1[j]};
            *(float2*)&As2[0][kr * A_STRIDE + 2 * lrow]       = d0;
            *(float2*)&As2[0][kr * A_STRIDE + 2 * lrow + 128] = d1;
            Bs[0][kr * B_STRIDE + lrow]      = bv0[j];
            Bs[0][kr * B_STRIDE + lrow + 64] = bv1[j];
        }
    }
    __syncthreads();

    int buf = 0;
    for (int kk = 0; kk < K_DIM; kk += 16) {
        const bool has_next = (kk + 16) < K_DIM;
        float4 na0, na1, nb0, nb1;
        if (has_next) {
            na0 = *(const float4*)(Ag + kk + 16);
            na1 = *(const float4*)(Ag + kk + 16 + (size_t)64 * K_DIM);
            nb0 = *(const float4*)(Bg + kk + 16);
            nb1 = *(const float4*)(Bg + kk + 16 + (size_t)64 * K_DIM);
        }

        const float* Ab = As2[buf];
        const float* Bb = Bs[buf];
        #pragma unroll
        for (int k = 0; k < 16; ++k) {
            ulonglong2 aA = *(const ulonglong2*)&Ab[k * A_STRIDE + 8 * ty];        // rows 4ty,4ty+1 (dup)
            ulonglong2 aB = *(const ulonglong2*)&Ab[k * A_STRIDE + 8 * ty + 4];    // rows 4ty+2,4ty+3
            ulonglong2 aC = *(const ulonglong2*)&Ab[k * A_STRIDE + 8 * ty + 128];  // rows 64+4ty,+1
            ulonglong2 aD = *(const ulonglong2*)&Ab[k * A_STRIDE + 8 * ty + 132];  // rows 64+4ty+2,+3
            ulonglong2 b0 = *(const ulonglong2*)&Bb[k * B_STRIDE + 4 * tx];        // cols 4tx..4tx+3
            ulonglong2 b1 = *(const ulonglong2*)&Bb[k * B_STRIDE + 4 * tx + 64];   // cols 64+4tx..+3
            u64 a_[8] = {aA.x, aA.y, aB.x, aB.y, aC.x, aC.y, aD.x, aD.y};
            u64 b_[4] = {b0.x, b0.y, b1.x, b1.y};
            #pragma unroll
            for (int i = 0; i < 8; i++) {
                fma2(acc[i][0], a_[i], b_[0]);
                fma2(acc[i][1], a_[i], b_[1]);
                fma2(acc[i][2], a_[i], b_[2]);
                fma2(acc[i][3], a_[i], b_[3]);
            }
        }

        if (has_next) {
            const int nb = buf ^ 1;
            float av0[4] = {na0.x, na0.y, na0.z, na0.w};
            float av1[4] = {na1.x, na1.y, na1.z, na1.w};
            float bw0[4] = {nb0.x, nb0.y, nb0.z, nb0.w};
            float bw1[4] = {nb1.x, nb1.y, nb1.z, nb1.w};
            #pragma unroll
            for (int j = 0; j < 4; j++) {
                const int kr = lk + j;
                float2 d0 = {av0[j], av0[j]};
                float2 d1 = {av1[j], av1[j]};
                *(float2*)&As2[nb][kr * A_STRIDE + 2 * lrow]       = d0;
                *(float2*)&As2[nb][kr * A_STRIDE + 2 * lrow + 128] = d1;
                Bs[nb][kr * B_STRIDE + lrow]      = bw0[j];
                Bs[nb][kr * B_STRIDE + lrow + 64] = bw1[j];
            }
            __syncthreads();
            buf = nb;
        }
    }

    // ---- epilogue: + bias, write g_y ----
    float bv[8];
    #pragma unroll
    for (int j = 0; j < 4; j++) bv[j]     = bias[bcol + (tx << 2) + j];
    #pragma unroll
    for (int j = 0; j < 4; j++) bv[4 + j] = bias[bcol + 64 + (tx << 2) + j];

    #pragma unroll
    for (int i = 0; i < 8; i++) {
        const int row = brow + ((i < 4) ? ((ty << 2) + i) : (64 + (ty << 2) + i - 4));
        float* cp = g_y + (size_t)row * N_COLS + bcol + (tx << 2);
        float2 f0 = unpack2(acc[i][0]);
        float2 f1 = unpack2(acc[i][1]);
        float2 f2 = unpack2(acc[i][2]);
        float2 f3 = unpack2(acc[i][3]);
        float4 o0 = {f0.x + bv[0], f0.y + bv[1], f1.x + bv[2], f1.y + bv[3]};
        float4 o1 = {f2.x + bv[4], f2.y + bv[5], f3.x + bv[6], f3.y + bv[7]};
        *(float4*)cp = o0;
        *(float4*)(cp + 64) = o1;
    }
}

// ---------------- 3. BN stats: per-row partial sums per t = col & 15 ------
__global__ __launch_bounds__(256) void stats_kernel() {
    const int row = blockIdx.x;
    const int tid = threadIdx.x;
    const float* yr = g_y + (size_t)row * N_COLS;
    float s = 0.f, q = 0.f;
    #pragma unroll 8
    for (int j = 0; j < 32; j++) {
        float v = yr[tid + (j << 8)];   // col % 16 == tid % 16 for all j
        s += v;
        q += v * v;
    }
    __shared__ float sh[512];
    sh[tid] = s;
    sh[256 + tid] = q;
    __syncthreads();
    if (tid < 32) {
        const int base = (tid < 16) ? tid : (256 + tid - 16);
        float a = 0.f;
        #pragma unroll
        for (int j = 0; j < 16; j++) a += sh[base + (j << 4)];
        g_part[row * 32 + tid] = a;
    }
}

__global__ __launch_bounds__(256) void reduce_kernel() {
    const int bin = blockIdx.x;
    const int tid = threadIdx.x;
    float s = 0.f;
    for (int r = tid; r < M_ROWS; r += 256) s += g_part[r * 32 + bin];
    __shared__ float sh[256];
    sh[tid] = s;
    __syncthreads();
    #pragma unroll
    for (int o = 128; o; o >>= 1) {
        if (tid < o) sh[tid] += sh[tid + o];
        __syncthreads();
    }
    if (!tid) g_bin[bin] = sh[0];
}

__global__ void finalize_kernel() {
    const int t = threadIdx.x;  // 16 threads
    float mean = g_bin[t] * (1.0f / (float)PER_T_COUNT);
    float ex2  = g_bin[16 + t] * (1.0f / (float)PER_T_COUNT);
    float var  = ex2 - mean * mean;
    g_stats[t] = mean;
    g_stats[16 + t] = 1.0f / sqrtf(var + 1e-5f);
}

// ---------------- 4. BN normalize + LIF scan + spike write ----------------
__global__ __launch_bounds__(256) void lif_kernel(const float* __restrict__ bng,
                                                  const float* __restrict__ bnb,
                                                  const float* __restrict__ th,
                                                  float* __restrict__ out) {
    __shared__ float sm[16], si[16], sg[16], sb[16];
    const int tid = threadIdx.x;
    if (tid < 16) {
        sm[tid] = g_stats[tid];
        si[tid] = g_stats[16 + tid];
        sg[tid] = bng[tid];
        sb[tid] = bnb[tid];
    }
    __syncthreads();
    const float thr = __ldg(th);

    const unsigned gid = blockIdx.x * 256u + tid;  // 0 .. 4194303
    const unsigned m = gid >> 9;
    const unsigned d = gid & 511u;

    const float4* yp = (const float4*)(g_y + ((size_t)m << 13) + ((size_t)d << 4));
    float4 v0 = yp[0], v1 = yp[1], v2 = yp[2], v3 = yp[3];
    float xs[16] = {v0.x, v0.y, v0.z, v0.w, v1.x, v1.y, v1.z, v1.w,
                    v2.x, v2.y, v2.z, v2.w, v3.x, v3.y, v3.z, v3.w};

    float v = 0.f;
    const size_t ob = ((size_t)m << 9) + d;
    #pragma unroll
    for (int t = 0; t < T_STEPS; t++) {
        float val = (xs[t] - sm[t]) * si[t];
        val = val * sg[t] + sb[t];
        v = v + (val - v) * 0.5f;          // v += (x - v)/tau, tau=2 (exact /2)
        bool fire = (v >= thr);            // spike_fn(v - thr): (v-thr)>=0 <=> v>=thr
        out[ob + ((size_t)t << 22)] = fire ? 1.0f : 0.0f;
        if (fire) v = 0.f;                 // hard reset to 0
    }
}

// ---------------- launch ---------------------------------------------------
extern "C" void kernel_launch(void* const* d_in, const int* in_sizes, int n_in,
                              void* d_out, int out_size) {
    const float* x    = (const float*)d_in[0];  // inputs (B,L,D)
    const float* Wm   = (const float*)d_in[1];  // W (D*T, D)
    const float* bias = (const float*)d_in[2];  // b (D*T)
    const float* lng  = (const float*)d_in[3];
    const float* lnb  = (const float*)d_in[4];
    const float* bng  = (const float*)d_in[5];
    const float* bnb  = (const float*)d_in[6];
    const float* th   = (const float*)d_in[7];
    float* out = (float*)d_out;

    ln_kernel<<<M_ROWS, 128>>>(x, lng, lnb);
    dim3 gg(N_COLS / 128, M_ROWS / 128);
    gemm_kernel<<<gg, 256>>>(Wm, bias);
    stats_kernel<<<M_ROWS, 256>>>();
    reduce_kernel<<<32, 256>>>();
    finalize_kernel<<<1, 16>>>();
    lif_kernel<<<(M_ROWS * K_DIM) / 256, 256>>>(bng, bnb, th, out);
}